// round 12
// baseline (speedup 1.0000x reference)
#include <cuda_runtime.h>
#include <cuda_bf16.h>

// Dequantize: out4[g] = codebooks[cb][code[g]] * scales[g/16]
//   cb = (g >= N_codes/2) ? 1 : 0   (codes buffer is [2, N/2] contiguous)
//
// 8 codes per thread, block-strided (idx = blockBase + tid + 256*k):
//   - codes + scales front-batched (MLP=8 LDG) into 16 regs
//   - gather/mul/store interleaved per k -> one live float4, low reg count
//   - guard-free fast path for full tiles (all blocks, for 2048-divisible N)
//   - all global accesses fully coalesced; output streaming (__stcs)

#define TPB   256
#define KPT   8   // codes per thread

__global__ __launch_bounds__(TPB)
void dequant_kernel(const float4* __restrict__ codebooks,   // 512 x float4
                    const float*  __restrict__ scales,
                    const int*    __restrict__ codes,        // N codes (i32)
                    float4*       __restrict__ out,          // N float4
                    int n_codes,
                    int half_codes)
{
    __shared__ float4 cb[512];

    #pragma unroll
    for (int i = threadIdx.x; i < 512; i += TPB)
        cb[i] = codebooks[i];
    __syncthreads();

    const int base = blockIdx.x * (TPB * KPT) + threadIdx.x;

    if (base + (KPT - 1) * TPB < n_codes) {
        // ---- fast path: whole tile in range, no predication ----
        int   c[KPT];
        float s[KPT];

        #pragma unroll
        for (int k = 0; k < KPT; k++)
            c[k] = __ldcs(&codes[base + k * TPB]);

        #pragma unroll
        for (int k = 0; k < KPT; k++)
            s[k] = __ldcs(&scales[(base + k * TPB) >> 4]);

        #pragma unroll
        for (int k = 0; k < KPT; k++) {
            int idx = base + k * TPB;
            float4 v = cb[c[k] + ((idx >= half_codes) ? 256 : 0)];
            float4 o;
            o.x = v.x * s[k];
            o.y = v.y * s[k];
            o.z = v.z * s[k];
            o.w = v.w * s[k];
            __stcs(&out[(size_t)idx], o);
        }
    } else {
        // ---- tail path ----
        #pragma unroll
        for (int k = 0; k < KPT; k++) {
            int idx = base + k * TPB;
            if (idx < n_codes) {
                int   cc = __ldcs(&codes[idx]) + ((idx >= half_codes) ? 256 : 0);
                float ss = __ldcs(&scales[idx >> 4]);
                float4 v = cb[cc];
                float4 o;
                o.x = v.x * ss;
                o.y = v.y * ss;
                o.z = v.z * ss;
                o.w = v.w * ss;
                __stcs(&out[(size_t)idx], o);
            }
        }
    }
}

extern "C" void kernel_launch(void* const* d_in, const int* in_sizes, int n_in,
                              void* d_out, int out_size)
{
    // metadata order: codebooks (f32), scales (f32), codes (i32), rows, columns
    const float4* codebooks = (const float4*)d_in[0];
    const float*  scales    = (const float*) d_in[1];
    const int*    codes     = (const int*)   d_in[2];
    float4*       out       = (float4*)      d_out;

    const int n_codes = in_sizes[2];     // numel / 4  (both codebooks)
    const int half    = n_codes / 2;

    const int per_block = TPB * KPT;
    const int blocks    = (n_codes + per_block - 1) / per_block;

    dequant_kernel<<<blocks, TPB>>>(codebooks, scales, codes, out, n_codes, half);
}

// round 13
// speedup vs baseline: 1.0364x; 1.0364x over previous
#include <cuda_runtime.h>
#include <cuda_bf16.h>

// Dequantize: out4[g] = codebooks[cb][code[g]] * scales[g/16]
//   cb = (g >= N_codes/2) ? 1 : 0   (codes buffer is [2, N/2] contiguous)
//
// Occupancy-first version (R11 showed occ=66%, nothing saturated):
//   - __launch_bounds__(256, 8): force <=32 regs -> 8 CTAs/SM
//   - codes front-batched (8 regs, DRAM MLP); scales loaded per-k (L1-hot:
//     consecutive k share the 128B scale line, reused by all warps of the CTA)
//   - codebook-half offset hoisted per block (tiles don't straddle the half)
//   - all global accesses fully coalesced; output streaming (__stcs)

#define TPB   256
#define KPT   8   // codes per thread

__global__ __launch_bounds__(TPB, 8)
void dequant_kernel(const float4* __restrict__ codebooks,   // 512 x float4
                    const float*  __restrict__ scales,
                    const int*    __restrict__ codes,        // N codes (i32)
                    float4*       __restrict__ out,          // N float4
                    int n_codes,
                    int half_codes)
{
    __shared__ float4 cb[512];

    #pragma unroll
    for (int i = threadIdx.x; i < 512; i += TPB)
        cb[i] = codebooks[i];
    __syncthreads();

    const int tile_lo = blockIdx.x * (TPB * KPT);
    const int base    = tile_lo + threadIdx.x;

    const bool full     = (tile_lo + TPB * KPT <= n_codes);
    const bool straddle = (tile_lo < half_codes) && (tile_lo + TPB * KPT > half_codes);

    if (full && !straddle) {
        // ---- fast path: no bounds predication, uniform codebook half ----
        const int off = (tile_lo >= half_codes) ? 256 : 0;

        int c[KPT];
        #pragma unroll
        for (int k = 0; k < KPT; k++)
            c[k] = __ldcs(&codes[base + k * TPB]);

        #pragma unroll
        for (int k = 0; k < KPT; k++) {
            const int idx = base + k * TPB;
            const float s = scales[idx >> 4];        // cached: reused across warps/k
            const float4 v = cb[c[k] + off];
            float4 o;
            o.x = v.x * s;
            o.y = v.y * s;
            o.z = v.z * s;
            o.w = v.w * s;
            __stcs(&out[(size_t)idx], o);
        }
    } else {
        // ---- tail / straddle path ----
        #pragma unroll
        for (int k = 0; k < KPT; k++) {
            const int idx = base + k * TPB;
            if (idx < n_codes) {
                const int   cc = __ldcs(&codes[idx]) + ((idx >= half_codes) ? 256 : 0);
                const float ss = scales[idx >> 4];
                const float4 v = cb[cc];
                float4 o;
                o.x = v.x * ss;
                o.y = v.y * ss;
                o.z = v.z * ss;
                o.w = v.w * ss;
                __stcs(&out[(size_t)idx], o);
            }
        }
    }
}

extern "C" void kernel_launch(void* const* d_in, const int* in_sizes, int n_in,
                              void* d_out, int out_size)
{
    // metadata order: codebooks (f32), scales (f32), codes (i32), rows, columns
    const float4* codebooks = (const float4*)d_in[0];
    const float*  scales    = (const float*) d_in[1];
    const int*    codes     = (const int*)   d_in[2];
    float4*       out       = (float4*)      d_out;

    const int n_codes = in_sizes[2];     // numel / 4  (both codebooks)
    const int half    = n_codes / 2;

    const int per_block = TPB * KPT;
    const int blocks    = (n_codes + per_block - 1) / per_block;

    dequant_kernel<<<blocks, TPB>>>(codebooks, scales, codes, out, n_codes, half);
}